// round 13
// baseline (speedup 1.0000x reference)
#include <cuda_runtime.h>
#include <cstdint>
#include <math.h>

#define B_    4
#define C_    256
#define H_    256
#define W_    256
#define HW_   (H_*W_)
#define M_    100
#define P_    7
#define NBINS 49
#define CCHUNK 32
#define TSTRIDE 33              // odd -> conflict-free cell-major tile
#define CELLMAX 184             // proven: spanx*spany <= ~179
#define PADCELLS 32             // absorbs zero-weight 3x3 patch overhang reads

// dynamic smem layout:
//   float  tile[(CELLMAX+PADCELLS)*TSTRIDE]  (28512 B)
//   float4 list[NBINS*3]                     (2352 B)
#define TILE_ALLOC ((CELLMAX + PADCELLS) * TSTRIDE)
#define SMEM_BYTES (TILE_ALLOC*4 + NBINS*3*16)

__device__ __forceinline__ void cp_async4(unsigned int saddr, const void* gptr) {
    asm volatile("cp.async.ca.shared.global [%0], [%1], 4;\n"
                 :: "r"(saddr), "l"(gptr) : "memory");
}

__global__ __launch_bounds__(256, 7)   // 7 CTAs/SM: waves 3.6 -> 3.09
void roialign_rot_kernel(const float* __restrict__ feature,
                         const float* __restrict__ boxes,
                         float* __restrict__ out)
{
    extern __shared__ float smem[];
    float*  tile = smem;
    float4* list = (float4*)(smem + TILE_ALLOC);

    const int bm = blockIdx.x;            // box id 0..399
    const int c0 = blockIdx.y * CCHUNK;   // channel chunk base
    const int tid = threadIdx.x;

    // ---- per-box parameters (broadcast; div-free + approx sincos) ----
    const float b0 = boxes[bm*7 + 0];
    const float b1 = boxes[bm*7 + 1];
    const float b4 = boxes[bm*7 + 4];
    const float b5 = boxes[bm*7 + 5];
    const float b6 = boxes[bm*7 + 6];

    const float inv_gw = 1.0f / 1.1f;
    const float inv_gh = 3.2f;

    const float cx = (b0 + 140.8f) * inv_gw - 0.5f;
    const float cy = (b1 + 40.0f)  * inv_gh - 0.5f;
    const float rw = b5 * inv_gw;
    const float rh = b4 * inv_gh;
    const float theta = -b6;
    const float bin_w = rw * (1.0f / 7.0f);
    const float bin_h = rh * (1.0f / 7.0f);

    float sinv, cosv;
    __sincosf(theta, &sinv, &cosv);        // samples never near validity boundary
    const float ac = fabsf(cosv), as = fabsf(sinv);

    // tight extent of the sample grid
    const float hw = rw * (13.0f / 28.0f);
    const float hh = rh * (13.0f / 28.0f);
    const float ax = hw * ac + hh * as + 0.01f;
    const float ay = hw * as + hh * ac + 0.01f;

    int ox = (int)floorf(cx - ax); if (ox < 0) ox = 0;
    int oy = (int)floorf(cy - ay); if (oy < 0) oy = 0;
    int ex = (int)floorf(cx + ax) + 1; if (ex > W_-1) ex = W_-1;
    int ey = (int)floorf(cy + ay) + 1; if (ey > H_-1) ey = H_-1;
    int spanx = ex - ox + 1; if (spanx < 1) spanx = 1;
    int spany = ey - oy + 1; if (spany < 1) spany = 1;
    if (ox > W_ - spanx) ox = W_ - spanx;
    if (oy > H_ - spany) oy = H_ - spany;
    if (spanx * spany > CELLMAX) { spany = CELLMAX / spanx; if (spany < 1) spany = 1; }
    const int ncell = spanx * spany;

    // ---- phase 1: async-copy the tight window into smem (2 threads / cell) ----
    {
        const int b = bm / M_;
        const float* fbase = feature + ((size_t)b * C_ + c0) * HW_;
        const unsigned int tile_s = (unsigned int)__cvta_generic_to_shared(tile);

        for (int i = tid; i < 2 * ncell; i += 256) {
            const int cell = i >> 1;
            const int ch0  = (i & 1) << 4;       // 0 or 16
            const int dy   = cell / spanx;
            const int dx   = cell - dy * spanx;
            const float* p = fbase + (size_t)ch0 * HW_ + (size_t)(oy + dy) * W_ + (ox + dx);
            unsigned int s = tile_s + (unsigned int)(cell * TSTRIDE + ch0) * 4u;
            #pragma unroll
            for (int c = 0; c < 16; c++) {
                cp_async4(s + 4u * c, p + (size_t)c * HW_);
            }
        }
        asm volatile("cp.async.commit_group;\n" ::: "memory");
    }

    // ---- phase 0: per-bin 3x3 merged patch, register-resident (49 threads) ----
    // (overlaps with cp.async flight)
    if (tid < NBINS) {
        const int py = tid / P_;
        const int px = tid - py * P_;

        // pass 1: min corner (origin) over the 4 samples
        int miny0 = H_ - 1, minx0 = W_ - 1;
        #pragma unroll
        for (int s = 0; s < 4; s++) {
            const int sy = s >> 1, sx = s & 1;
            const float yy = -0.5f * rh + bin_h * ((float)py + ((float)sy + 0.5f) * 0.5f);
            const float xx = -0.5f * rw + bin_w * ((float)px + ((float)sx + 0.5f) * 0.5f);
            float y = yy * cosv - xx * sinv + cy;
            float x = yy * sinv + xx * cosv + cx;
            y = fmaxf(y, 0.0f);
            x = fmaxf(x, 0.0f);
            int y0 = (int)floorf(y); if (y0 > H_-1) y0 = H_-1;
            int x0 = (int)floorf(x); if (x0 > W_-1) x0 = W_-1;
            miny0 = min(miny0, y0);
            minx0 = min(minx0, x0);
        }

        // pass 2: weights into the 3x3 patch (offsets proven in [0,2])
        float w9[9];
        #pragma unroll
        for (int k = 0; k < 9; k++) w9[k] = 0.0f;

        #pragma unroll
        for (int s = 0; s < 4; s++) {
            const int sy = s >> 1, sx = s & 1;
            const float yy = -0.5f * rh + bin_h * ((float)py + ((float)sy + 0.5f) * 0.5f);
            const float xx = -0.5f * rw + bin_w * ((float)px + ((float)sx + 0.5f) * 0.5f);
            float y = yy * cosv - xx * sinv + cy;
            float x = yy * sinv + xx * cosv + cx;

            const bool valid = (y > -1.0f) && (y < (float)H_) && (x > -1.0f) && (x < (float)W_);

            y = fmaxf(y, 0.0f);
            x = fmaxf(x, 0.0f);
            int y0 = (int)floorf(y); if (y0 > H_-1) y0 = H_-1;
            int x0 = (int)floorf(x); if (x0 > W_-1) x0 = W_-1;
            int y1 = y0 + 1; if (y1 > H_-1) y1 = H_-1;
            int x1 = x0 + 1; if (x1 > W_-1) x1 = W_-1;
            if (y0 >= H_-1) y = (float)y0;
            if (x0 >= W_-1) x = (float)x0;
            const float ly = y - (float)y0;
            const float lx = x - (float)x0;
            const float hy = 1.0f - ly;
            const float hx = 1.0f - lx;

            const float vm = valid ? 0.25f : 0.0f;
            const float w00 = hy * hx * vm;
            const float w01 = hy * lx * vm;
            const float w10 = ly * hx * vm;
            const float w11 = ly * lx * vm;

            int dy0 = y0 - miny0; if (dy0 < 0) dy0 = 0; if (dy0 > 2) dy0 = 2;
            int dx0 = x0 - minx0; if (dx0 < 0) dx0 = 0; if (dx0 > 2) dx0 = 2;
            int dy1 = y1 - miny0; if (dy1 < 0) dy1 = 0; if (dy1 > 2) dy1 = 2;
            int dx1 = x1 - minx0; if (dx1 < 0) dx1 = 0; if (dx1 > 2) dx1 = 2;

            const int s00 = dy0 * 3 + dx0;
            const int s01 = dy0 * 3 + dx1;
            const int s10 = dy1 * 3 + dx0;
            const int s11 = dy1 * 3 + dx1;

            #pragma unroll
            for (int k = 0; k < 9; k++) {
                w9[k] += (s00 == k) ? w00 : 0.0f;
                w9[k] += (s01 == k) ? w01 : 0.0f;
                w9[k] += (s10 == k) ? w10 : 0.0f;
                w9[k] += (s11 == k) ? w11 : 0.0f;
            }
        }

        const int base = ((miny0 - oy) * spanx + (minx0 - ox)) * TSTRIDE;

        float4* lp = list + tid * 3;
        lp[0] = make_float4(__int_as_float(base), w9[0], w9[1], w9[2]);
        lp[1] = make_float4(w9[3], w9[4], w9[5], w9[6]);
        lp[2] = make_float4(w9[7], w9[8], 0.0f, 0.0f);
    }

    asm volatile("cp.async.wait_group 0;\n" ::: "memory");
    __syncthreads();

    // ---- phase 2: pooled output, 2 bins in flight (independent chains) ----
    {
        const int c = tid & (CCHUNK - 1);   // 0..31
        const int g = tid >> 5;             // warp id -> uniform bin per warp
        float* outp = out + (size_t)bm * (NBINS * C_) + c0 + c;
        const int rowT = spanx * TSTRIDE;

        #pragma unroll
        for (int kb = 0; kb < 4; kb++) {
            const int binA = g + 16 * kb;        // 0..7, 16..23, 32..39, 48..55
            const int binB = binA + 8;
            if (binA >= NBINS) break;

            const float4 a0 = list[binA * 3 + 0];
            const float4 a1 = list[binA * 3 + 1];
            const float4 a2 = list[binA * 3 + 2];
            const float* ta = tile + __float_as_int(a0.x) + c;

            float accA;
            accA  = a0.y * ta[0];
            accA += a0.z * ta[TSTRIDE];
            accA += a0.w * ta[2 * TSTRIDE];
            accA += a1.x * ta[rowT];
            accA += a1.y * ta[rowT + TSTRIDE];
            accA += a1.z * ta[rowT + 2 * TSTRIDE];
            accA += a1.w * ta[2 * rowT];
            accA += a2.x * ta[2 * rowT + TSTRIDE];
            accA += a2.y * ta[2 * rowT + 2 * TSTRIDE];
            outp[(size_t)binA * C_] = accA;

            if (binB < NBINS) {
                const float4 q0 = list[binB * 3 + 0];
                const float4 q1 = list[binB * 3 + 1];
                const float4 q2 = list[binB * 3 + 2];
                const float* tb = tile + __float_as_int(q0.x) + c;

                float accB;
                accB  = q0.y * tb[0];
                accB += q0.z * tb[TSTRIDE];
                accB += q0.w * tb[2 * TSTRIDE];
                accB += q1.x * tb[rowT];
                accB += q1.y * tb[rowT + TSTRIDE];
                accB += q1.z * tb[rowT + 2 * TSTRIDE];
                accB += q1.w * tb[2 * rowT];
                accB += q2.x * tb[2 * rowT + TSTRIDE];
                accB += q2.y * tb[2 * rowT + 2 * TSTRIDE];
                outp[(size_t)binB * C_] = accB;
            }
        }
    }
}

extern "C" void kernel_launch(void* const* d_in, const int* in_sizes, int n_in,
                              void* d_out, int out_size)
{
    const float* feature = (const float*)d_in[0];
    const float* boxes   = (const float*)d_in[1];
    float* out = (float*)d_out;

    cudaFuncSetAttribute(roialign_rot_kernel,
                         cudaFuncAttributeMaxDynamicSharedMemorySize, SMEM_BYTES);

    dim3 grid(B_ * M_, C_ / CCHUNK);   // 400 x 8
    roialign_rot_kernel<<<grid, 256, SMEM_BYTES>>>(feature, boxes, out);
}

// round 14
// speedup vs baseline: 1.5380x; 1.5380x over previous
#include <cuda_runtime.h>
#include <cstdint>
#include <math.h>

#define B_    4
#define C_    256
#define H_    256
#define W_    256
#define HW_   (H_*W_)
#define M_    100
#define P_    7
#define NBINS 49
#define CCHUNK 32
#define TSTRIDE 33              // odd -> conflict-free cell-major tile
#define CELLMAX 184             // proven: spanx*spany <= ~179
#define PADCELLS 32             // absorbs zero-weight 3x3 patch overhang reads

// dynamic smem layout:
//   float  tile[(CELLMAX+PADCELLS)*TSTRIDE]  (28512 B)
//   float4 list[NBINS*3]                     (2352 B)
#define TILE_ALLOC ((CELLMAX + PADCELLS) * TSTRIDE)
#define SMEM_BYTES (TILE_ALLOC*4 + NBINS*3*16)

__device__ __forceinline__ void cp_async4(unsigned int saddr, const void* gptr) {
    asm volatile("cp.async.ca.shared.global [%0], [%1], 4;\n"
                 :: "r"(saddr), "l"(gptr) : "memory");
}

__global__ __launch_bounds__(256, 6)   // 42-reg budget: phase-0 fits at 40, NO spills
void roialign_rot_kernel(const float* __restrict__ feature,
                         const float* __restrict__ boxes,
                         float* __restrict__ out)
{
    extern __shared__ float smem[];
    float*  tile = smem;
    float4* list = (float4*)(smem + TILE_ALLOC);

    const int bm = blockIdx.x;            // box id 0..399
    const int c0 = blockIdx.y * CCHUNK;   // channel chunk base
    const int tid = threadIdx.x;

    // ---- per-box parameters (broadcast; div-free + approx sincos) ----
    const float b0 = boxes[bm*7 + 0];
    const float b1 = boxes[bm*7 + 1];
    const float b4 = boxes[bm*7 + 4];
    const float b5 = boxes[bm*7 + 5];
    const float b6 = boxes[bm*7 + 6];

    const float inv_gw = 1.0f / 1.1f;
    const float inv_gh = 3.2f;

    const float cx = (b0 + 140.8f) * inv_gw - 0.5f;
    const float cy = (b1 + 40.0f)  * inv_gh - 0.5f;
    const float rw = b5 * inv_gw;
    const float rh = b4 * inv_gh;
    const float theta = -b6;
    const float bin_w = rw * (1.0f / 7.0f);
    const float bin_h = rh * (1.0f / 7.0f);

    float sinv, cosv;
    __sincosf(theta, &sinv, &cosv);        // samples never near validity boundary
    const float ac = fabsf(cosv), as = fabsf(sinv);

    // tight extent of the sample grid
    const float hw = rw * (13.0f / 28.0f);
    const float hh = rh * (13.0f / 28.0f);
    const float ax = hw * ac + hh * as + 0.01f;
    const float ay = hw * as + hh * ac + 0.01f;

    int ox = (int)floorf(cx - ax); if (ox < 0) ox = 0;
    int oy = (int)floorf(cy - ay); if (oy < 0) oy = 0;
    int ex = (int)floorf(cx + ax) + 1; if (ex > W_-1) ex = W_-1;
    int ey = (int)floorf(cy + ay) + 1; if (ey > H_-1) ey = H_-1;
    int spanx = ex - ox + 1; if (spanx < 1) spanx = 1;
    int spany = ey - oy + 1; if (spany < 1) spany = 1;
    if (ox > W_ - spanx) ox = W_ - spanx;
    if (oy > H_ - spany) oy = H_ - spany;
    if (spanx * spany > CELLMAX) { spany = CELLMAX / spanx; if (spany < 1) spany = 1; }
    const int ncell = spanx * spany;

    // ---- phase 1: async-copy the tight window into smem (2 threads / cell) ----
    {
        const int b = bm / M_;
        const float* fbase = feature + ((size_t)b * C_ + c0) * HW_;
        const unsigned int tile_s = (unsigned int)__cvta_generic_to_shared(tile);

        for (int i = tid; i < 2 * ncell; i += 256) {
            const int cell = i >> 1;
            const int ch0  = (i & 1) << 4;       // 0 or 16
            const int dy   = cell / spanx;
            const int dx   = cell - dy * spanx;
            const float* p = fbase + (size_t)ch0 * HW_ + (size_t)(oy + dy) * W_ + (ox + dx);
            unsigned int s = tile_s + (unsigned int)(cell * TSTRIDE + ch0) * 4u;
            #pragma unroll
            for (int c = 0; c < 16; c++) {
                cp_async4(s + 4u * c, p + (size_t)c * HW_);
            }
        }
        asm volatile("cp.async.commit_group;\n" ::: "memory");
    }

    // ---- phase 0: per-bin 3x3 merged patch, register-resident (49 threads) ----
    // (overlaps with cp.async flight)
    if (tid < NBINS) {
        const int py = tid / P_;
        const int px = tid - py * P_;

        // pass 1: min corner (origin) over the 4 samples
        int miny0 = H_ - 1, minx0 = W_ - 1;
        #pragma unroll
        for (int s = 0; s < 4; s++) {
            const int sy = s >> 1, sx = s & 1;
            const float yy = -0.5f * rh + bin_h * ((float)py + ((float)sy + 0.5f) * 0.5f);
            const float xx = -0.5f * rw + bin_w * ((float)px + ((float)sx + 0.5f) * 0.5f);
            float y = yy * cosv - xx * sinv + cy;
            float x = yy * sinv + xx * cosv + cx;
            y = fmaxf(y, 0.0f);
            x = fmaxf(x, 0.0f);
            int y0 = (int)floorf(y); if (y0 > H_-1) y0 = H_-1;
            int x0 = (int)floorf(x); if (x0 > W_-1) x0 = W_-1;
            miny0 = min(miny0, y0);
            minx0 = min(minx0, x0);
        }

        // pass 2: weights into the 3x3 patch (offsets proven in [0,2])
        float w9[9];
        #pragma unroll
        for (int k = 0; k < 9; k++) w9[k] = 0.0f;

        #pragma unroll
        for (int s = 0; s < 4; s++) {
            const int sy = s >> 1, sx = s & 1;
            const float yy = -0.5f * rh + bin_h * ((float)py + ((float)sy + 0.5f) * 0.5f);
            const float xx = -0.5f * rw + bin_w * ((float)px + ((float)sx + 0.5f) * 0.5f);
            float y = yy * cosv - xx * sinv + cy;
            float x = yy * sinv + xx * cosv + cx;

            const bool valid = (y > -1.0f) && (y < (float)H_) && (x > -1.0f) && (x < (float)W_);

            y = fmaxf(y, 0.0f);
            x = fmaxf(x, 0.0f);
            int y0 = (int)floorf(y); if (y0 > H_-1) y0 = H_-1;
            int x0 = (int)floorf(x); if (x0 > W_-1) x0 = W_-1;
            int y1 = y0 + 1; if (y1 > H_-1) y1 = H_-1;
            int x1 = x0 + 1; if (x1 > W_-1) x1 = W_-1;
            if (y0 >= H_-1) y = (float)y0;
            if (x0 >= W_-1) x = (float)x0;
            const float ly = y - (float)y0;
            const float lx = x - (float)x0;
            const float hy = 1.0f - ly;
            const float hx = 1.0f - lx;

            const float vm = valid ? 0.25f : 0.0f;
            const float w00 = hy * hx * vm;
            const float w01 = hy * lx * vm;
            const float w10 = ly * hx * vm;
            const float w11 = ly * lx * vm;

            int dy0 = y0 - miny0; if (dy0 < 0) dy0 = 0; if (dy0 > 2) dy0 = 2;
            int dx0 = x0 - minx0; if (dx0 < 0) dx0 = 0; if (dx0 > 2) dx0 = 2;
            int dy1 = y1 - miny0; if (dy1 < 0) dy1 = 0; if (dy1 > 2) dy1 = 2;
            int dx1 = x1 - minx0; if (dx1 < 0) dx1 = 0; if (dx1 > 2) dx1 = 2;

            const int s00 = dy0 * 3 + dx0;
            const int s01 = dy0 * 3 + dx1;
            const int s10 = dy1 * 3 + dx0;
            const int s11 = dy1 * 3 + dx1;

            #pragma unroll
            for (int k = 0; k < 9; k++) {
                w9[k] += (s00 == k) ? w00 : 0.0f;
                w9[k] += (s01 == k) ? w01 : 0.0f;
                w9[k] += (s10 == k) ? w10 : 0.0f;
                w9[k] += (s11 == k) ? w11 : 0.0f;
            }
        }

        const int base = ((miny0 - oy) * spanx + (minx0 - ox)) * TSTRIDE;

        float4* lp = list + tid * 3;
        lp[0] = make_float4(__int_as_float(base), w9[0], w9[1], w9[2]);
        lp[1] = make_float4(w9[3], w9[4], w9[5], w9[6]);
        lp[2] = make_float4(w9[7], w9[8], 0.0f, 0.0f);
    }

    asm volatile("cp.async.wait_group 0;\n" ::: "memory");
    __syncthreads();

    // ---- phase 2: pooled output, 2 bins in flight (independent chains) ----
    {
        const int c = tid & (CCHUNK - 1);   // 0..31
        const int g = tid >> 5;             // warp id -> uniform bin per warp
        float* outp = out + (size_t)bm * (NBINS * C_) + c0 + c;
        const int rowT = spanx * TSTRIDE;

        #pragma unroll
        for (int kb = 0; kb < 4; kb++) {
            const int binA = g + 16 * kb;        // 0..7, 16..23, 32..39, 48..55
            const int binB = binA + 8;
            if (binA >= NBINS) break;

            const float4 a0 = list[binA * 3 + 0];
            const float4 a1 = list[binA * 3 + 1];
            const float4 a2 = list[binA * 3 + 2];
            const float* ta = tile + __float_as_int(a0.x) + c;

            float accA;
            accA  = a0.y * ta[0];
            accA += a0.z * ta[TSTRIDE];
            accA += a0.w * ta[2 * TSTRIDE];
            accA += a1.x * ta[rowT];
            accA += a1.y * ta[rowT + TSTRIDE];
            accA += a1.z * ta[rowT + 2 * TSTRIDE];
            accA += a1.w * ta[2 * rowT];
            accA += a2.x * ta[2 * rowT + TSTRIDE];
            accA += a2.y * ta[2 * rowT + 2 * TSTRIDE];
            outp[(size_t)binA * C_] = accA;

            if (binB < NBINS) {
                const float4 q0 = list[binB * 3 + 0];
                const float4 q1 = list[binB * 3 + 1];
                const float4 q2 = list[binB * 3 + 2];
                const float* tb = tile + __float_as_int(q0.x) + c;

                float accB;
                accB  = q0.y * tb[0];
                accB += q0.z * tb[TSTRIDE];
                accB += q0.w * tb[2 * TSTRIDE];
                accB += q1.x * tb[rowT];
                accB += q1.y * tb[rowT + TSTRIDE];
                accB += q1.z * tb[rowT + 2 * TSTRIDE];
                accB += q1.w * tb[2 * rowT];
                accB += q2.x * tb[2 * rowT + TSTRIDE];
                accB += q2.y * tb[2 * rowT + 2 * TSTRIDE];
                outp[(size_t)binB * C_] = accB;
            }
        }
    }
}

extern "C" void kernel_launch(void* const* d_in, const int* in_sizes, int n_in,
                              void* d_out, int out_size)
{
    const float* feature = (const float*)d_in[0];
    const float* boxes   = (const float*)d_in[1];
    float* out = (float*)d_out;

    cudaFuncSetAttribute(roialign_rot_kernel,
                         cudaFuncAttributeMaxDynamicSharedMemorySize, SMEM_BYTES);

    dim3 grid(B_ * M_, C_ / CCHUNK);   // 400 x 8
    roialign_rot_kernel<<<grid, 256, SMEM_BYTES>>>(feature, boxes, out);
}